// round 13
// baseline (speedup 1.0000x reference)
#include <cuda_runtime.h>
#include <cuda_bf16.h>
#include <cstdint>

#define N_NODES 50000
#define N_EDGES 640000
#define NPAD    50048      // 391 * 128
#define SCAN_BLK 512
#define SCAN_NBLK ((N_NODES + SCAN_BLK - 1) / SCAN_BLK)   // 98

// ---------------- device scratch ----------------------------------------------
__device__ alignas(16)  int      g_is64;
__device__ alignas(16)  int      g_src[N_EDGES];
__device__ alignas(16)  int      g_dst[N_EDGES];
__device__ alignas(16)  int      g_cnt[N_NODES];
__device__ alignas(16)  int      g_rowptr[N_NODES + 1];
__device__ alignas(16)  int      g_fill[N_NODES];
__device__ alignas(16)  int      g_perm[N_EDGES];
__device__ alignas(16)  unsigned g_state[SCAN_NBLK];  // 0 | (1u<<30|agg) | (2u<<30|inc)
__device__ alignas(256) float    g_mean1[(size_t)NPAD * 128];
__device__ alignas(256) float    g_h[(size_t)NPAD * 256];
__device__ alignas(256) float    g_pr[(size_t)NPAD * 256];  // [p | r] for layer 2

// ---------------- zero + edge dtype detection (merged) -------------------------
__global__ void k_zero_cnt(const int* __restrict__ ei32) {
    int i = blockIdx.x * blockDim.x + threadIdx.x;
    if (i < N_NODES) g_cnt[i] = 0;
    if (i < SCAN_NBLK) g_state[i] = 0u;
    if (i == 0) {
        int is64 = 1;
        for (int j = 0; j < 64; j++)
            if (ei32[2 * j + 1] != 0) { is64 = 0; break; }
        g_is64 = is64;
    }
}

__global__ void k_conv_hist(const int* __restrict__ ei32) {
    int i = blockIdx.x * blockDim.x + threadIdx.x;
    if (i >= N_EDGES) return;
    int s, d;
    if (g_is64) {
        s = ei32[2 * i];
        d = ei32[2 * (N_EDGES + i)];
    } else {
        s = ei32[i];
        d = ei32[N_EDGES + i];
    }
    s = min(max(s, 0), N_NODES - 1);
    d = min(max(d, 0), N_NODES - 1);
    g_src[i] = s;
    g_dst[i] = d;
    atomicAdd(&g_cnt[d], 1);
}

// ---------------- single-kernel decoupled-lookback scan (unsigned state) -------
__global__ void k_scan_lb() {
    __shared__ int s[SCAN_BLK];
    __shared__ int s_excl;
    const int b = blockIdx.x;
    const int t = threadIdx.x;
    const int i = b * SCAN_BLK + t;
    const int v = (i < N_NODES) ? g_cnt[i] : 0;
    s[t] = v;
    __syncthreads();
#pragma unroll
    for (int off = 1; off < SCAN_BLK; off <<= 1) {
        int u = 0;
        if (t >= off) u = s[t - off];
        __syncthreads();
        if (t >= off) s[t] += u;
        __syncthreads();
    }
    const int total = s[SCAN_BLK - 1];

    if (t == 0) {
        constexpr unsigned VMASK = (1u << 30) - 1u;
        if (b == 0) {
            s_excl = 0;
            atomicExch(&g_state[0], (2u << 30) | (unsigned)total);
        } else {
            atomicExch(&g_state[b], (1u << 30) | (unsigned)total);
            int excl = 0;
            int p = b - 1;
            while (p >= 0) {
                unsigned w;
                do { w = atomicAdd(&g_state[p], 0u); } while (w == 0u);
                excl += (int)(w & VMASK);
                if ((w >> 30) == 2u) break;
                p--;
            }
            s_excl = excl;
            atomicExch(&g_state[b], (2u << 30) | (unsigned)(excl + total));
        }
    }
    __syncthreads();
    const int excl = s_excl;

    if (i < N_NODES) {
        const int r = excl + s[t] - v;   // global exclusive prefix
        g_rowptr[i] = r;
        g_fill[i]   = r;
    }
    if (i == 0) g_rowptr[N_NODES] = N_EDGES;
}

__global__ void k_scatter() {
    int i = blockIdx.x * blockDim.x + threadIdx.x;
    if (i < N_EDGES) {
        int pos = atomicAdd(&g_fill[g_dst[i]], 1);
        g_perm[pos] = g_src[i];
    }
}

// ---------------- layer-1 aggregation: warp per node ---------------------------
__global__ void k_agg1(const float* __restrict__ x) {
    const int node = (blockIdx.x * blockDim.x + threadIdx.x) >> 5;
    const int lane = threadIdx.x & 31;
    if (node >= N_NODES) return;
    const int beg = g_rowptr[node];
    const int end = g_rowptr[node + 1];
    float4 acc = make_float4(0.f, 0.f, 0.f, 0.f);
    for (int e = beg; e < end; e++) {
        const int s = g_perm[e];
        float4 v = ((const float4*)(x + (size_t)s * 128))[lane];
        acc.x += v.x; acc.y += v.y; acc.z += v.z; acc.w += v.w;
    }
    const float inv = 1.0f / (float)max(end - beg, 1);
    acc.x *= inv; acc.y *= inv; acc.z *= inv; acc.w *= inv;
    ((float4*)(g_mean1 + (size_t)node * 128))[lane] = acc;
}

// ---------------- layer-2 aggregation + epilogue -------------------------------
__global__ void k_agg2b(const float* __restrict__ bias, float* __restrict__ out) {
    const int node = (blockIdx.x * blockDim.x + threadIdx.x) >> 5;
    const int lane = threadIdx.x & 31;
    if (node >= N_NODES) return;
    const int beg = g_rowptr[node];
    const int end = g_rowptr[node + 1];
    float4 acc = make_float4(0.f, 0.f, 0.f, 0.f);
    for (int e = beg; e < end; e++) {
        const int s = g_perm[e];
        float4 v = ((const float4*)(g_pr + (size_t)s * 256))[lane];
        acc.x += v.x; acc.y += v.y; acc.z += v.z; acc.w += v.w;
    }
    const float inv = 1.0f / (float)max(end - beg, 1);
    float4 r = ((const float4*)(g_pr + (size_t)node * 256 + 128))[lane];
    float4 b = ((const float4*)bias)[lane];
    float4 o;
    o.x = acc.x * inv + r.x + b.x;
    o.y = acc.y * inv + r.y + b.y;
    o.z = acc.z * inv + r.z + b.z;
    o.w = acc.w * inv + r.w + b.w;
    ((float4*)(out + (size_t)node * 128))[lane] = o;
}

// ---------------- tf32 tensor-core GEMM, cp.async 3-stage pipeline -------------
__device__ __forceinline__ uint32_t f2tf32(float f) {
    uint32_t r;
    asm("cvt.rna.tf32.f32 %0, %1;" : "=r"(r) : "f"(f));
    return r;
}
__device__ __forceinline__ uint32_t bits2tf32(uint32_t b) {
    return f2tf32(__uint_as_float(b));
}

__device__ __forceinline__ void mma_tf32(float d[4], uint32_t a0, uint32_t a1,
                                         uint32_t a2, uint32_t a3,
                                         uint32_t b0, uint32_t b1) {
    asm volatile(
        "mma.sync.aligned.m16n8k8.row.col.f32.tf32.tf32.f32 "
        "{%0,%1,%2,%3}, {%4,%5,%6,%7}, {%8,%9}, {%0,%1,%2,%3};"
        : "+f"(d[0]), "+f"(d[1]), "+f"(d[2]), "+f"(d[3])
        : "r"(a0), "r"(a1), "r"(a2), "r"(a3), "r"(b0), "r"(b1));
}

#define CP_ASYNC16(saddr, gptr) \
    asm volatile("cp.async.cg.shared.global [%0], [%1], 16;" \
                 :: "r"(saddr), "l"(gptr))
#define CP_COMMIT()  asm volatile("cp.async.commit_group;" ::: "memory")
#define CP_WAIT_2()  asm volatile("cp.async.wait_group 2;" ::: "memory")
#define CP_WAIT_1()  asm volatile("cp.async.wait_group 1;" ::: "memory")
#define CP_WAIT_0()  asm volatile("cp.async.wait_group 0;" ::: "memory")

constexpr int GBM = 128, GBK = 32;
constexpr int GAS = 36;    // A smem row stride (floats)
constexpr int GBS = 136;   // B smem row stride (floats)
constexpr int GSTAGE = GBM * GAS + GBK * GBS;        // uint32 elems per stage
constexpr int GNSTG = 3;
constexpr int GSMEM_BYTES = GNSTG * GSTAGE * 4;      // 107520

template <bool RELU>
__device__ __forceinline__ void
tgemm(const float* __restrict__ A1, int K1, const float* __restrict__ B1,
      const float* __restrict__ A2, int K2, const float* __restrict__ B2,
      int ldb, int bofs, const float* __restrict__ bias,
      float* __restrict__ C, int ldc, int Mstore, int Mclamp) {
    extern __shared__ uint32_t smem[];

    const int tid  = threadIdx.x;
    const int wid  = tid >> 5;
    const int lane = tid & 31;
    const int wm = wid & 1;
    const int wn = wid >> 1;
    const int brow = blockIdx.y * GBM;

    const int nk1  = K1 >> 5;
    const int ntot = nk1 + (K2 >> 5);
    const uint32_t smem_u32 = (uint32_t)__cvta_generic_to_shared(smem);

    float acc[4][4][4];
#pragma unroll
    for (int mt = 0; mt < 4; mt++)
#pragma unroll
        for (int nt = 0; nt < 4; nt++)
#pragma unroll
            for (int r = 0; r < 4; r++) acc[mt][nt][r] = 0.f;

#define TG_ISSUE(IT)                                                           \
    do {                                                                       \
        const float* A_; const float* B_; int K_, k0_;                         \
        if ((IT) < nk1) { A_ = A1; B_ = B1; K_ = K1; k0_ = (IT) * GBK; }       \
        else            { A_ = A2; B_ = B2; K_ = K2; k0_ = ((IT) - nk1) * GBK;}\
        const uint32_t sa = smem_u32 + ((IT) % GNSTG) * (GSTAGE * 4);          \
        const uint32_t sb = sa + GBM * GAS * 4;                                \
        _Pragma("unroll")                                                      \
        for (int p = 0; p < 4; p++) {                                          \
            const int idx = tid + p * 256;                                     \
            const int row = idx >> 3;                                          \
            const int c4  = (idx & 7) << 2;                                    \
            const int rg  = min(brow + row, Mclamp - 1);                       \
            CP_ASYNC16(sa + (row * GAS + c4) * 4,                              \
                       &A_[(size_t)rg * K_ + k0_ + c4]);                       \
        }                                                                      \
        _Pragma("unroll")                                                      \
        for (int p = 0; p < 4; p++) {                                          \
            const int idx = tid + p * 256;                                     \
            const int row = idx >> 5;                                          \
            const int c4  = (idx & 31) << 2;                                   \
            CP_ASYNC16(sb + (row * GBS + c4) * 4,                              \
                       &B_[(size_t)(k0_ + row) * ldb + bofs + c4]);            \
        }                                                                      \
        CP_COMMIT();                                                           \
    } while (0)

    TG_ISSUE(0);
    if (1 < ntot) TG_ISSUE(1);

#pragma unroll 1
    for (int it = 0; it < ntot; it++) {
        if (it + 2 < ntot) {
            TG_ISSUE(it + 2);
            CP_WAIT_2();       // stage `it` complete (2 newer groups pending)
        } else if (it + 1 < ntot) {
            CP_WAIT_1();
        } else {
            CP_WAIT_0();
        }
        __syncthreads();

        const uint32_t* Asb = smem + (it % GNSTG) * GSTAGE;
        const uint32_t* Bsb = Asb + GBM * GAS;

#pragma unroll
        for (int ks = 0; ks < 4; ks++) {
            const int kk = ks * 8;
            uint32_t af[4][4];
#pragma unroll
            for (int mt = 0; mt < 4; mt++) {
                const int r = wm * 64 + mt * 16 + (lane >> 2);
                const int c = kk + (lane & 3);
                af[mt][0] = bits2tf32(Asb[r * GAS + c]);
                af[mt][1] = bits2tf32(Asb[(r + 8) * GAS + c]);
                af[mt][2] = bits2tf32(Asb[r * GAS + c + 4]);
                af[mt][3] = bits2tf32(Asb[(r + 8) * GAS + c + 4]);
            }
            uint32_t bf[4][2];
#pragma unroll
            for (int nt = 0; nt < 4; nt++) {
                const int n = wn * 32 + nt * 8 + (lane >> 2);
                const int k = kk + (lane & 3);
                bf[nt][0] = bits2tf32(Bsb[k * GBS + n]);
                bf[nt][1] = bits2tf32(Bsb[(k + 4) * GBS + n]);
            }
#pragma unroll
            for (int mt = 0; mt < 4; mt++)
#pragma unroll
                for (int nt = 0; nt < 4; nt++)
                    mma_tf32(acc[mt][nt], af[mt][0], af[mt][1], af[mt][2],
                             af[mt][3], bf[nt][0], bf[nt][1]);
        }
        __syncthreads();
    }
#undef TG_ISSUE

    const int bcolC = blockIdx.x * 128;
#pragma unroll
    for (int nt = 0; nt < 4; nt++) {
        const int col = bcolC + wn * 32 + nt * 8 + ((lane & 3) << 1);
        float bx = 0.f, by = 0.f;
        if (bias) { bx = bias[col]; by = bias[col + 1]; }
#pragma unroll
        for (int mt = 0; mt < 4; mt++) {
            const int row0 = brow + wm * 64 + mt * 16 + (lane >> 2);
            float2 v0, v1;
            v0.x = acc[mt][nt][0] + bx;  v0.y = acc[mt][nt][1] + by;
            v1.x = acc[mt][nt][2] + bx;  v1.y = acc[mt][nt][3] + by;
            if (RELU) {
                v0.x = fmaxf(v0.x, 0.f); v0.y = fmaxf(v0.y, 0.f);
                v1.x = fmaxf(v1.x, 0.f); v1.y = fmaxf(v1.y, 0.f);
            }
            if (row0 < Mstore)
                *(float2*)&C[(size_t)row0 * ldc + col] = v0;
            if (row0 + 8 < Mstore)
                *(float2*)&C[(size_t)(row0 + 8) * ldc + col] = v1;
        }
    }
}

__global__ void __launch_bounds__(256)
k_gemm1(const float* __restrict__ x,
        const float* __restrict__ B1, const float* __restrict__ B2,
        const float* __restrict__ bias) {
    const int bofs = blockIdx.x * 128;
    tgemm<true>(g_mean1, 128, B1, x, 128, B2, 256, bofs, bias,
                g_h, 256, N_NODES, N_NODES);
}

__global__ void __launch_bounds__(256)
k_gemm2(const float* __restrict__ w2l, const float* __restrict__ w2r) {
    const float* B = blockIdx.x ? w2r : w2l;
    tgemm<false>(g_h, 256, B, nullptr, 0, nullptr, 128, 0, nullptr,
                 g_pr, 256, N_NODES, N_NODES);
}

// ---------------- launch -------------------------------------------------------
extern "C" void kernel_launch(void* const* d_in, const int* in_sizes, int n_in,
                              void* d_out, int out_size) {
    const float* x    = (const float*)d_in[0];
    const int*   ei32 = (const int*)d_in[1];
    const float* w1_l = (const float*)d_in[2];
    const float* b1_l = (const float*)d_in[3];
    const float* w1_r = (const float*)d_in[4];
    const float* w2_l = (const float*)d_in[5];
    const float* b2_l = (const float*)d_in[6];
    const float* w2_r = (const float*)d_in[7];
    float* out = (float*)d_out;

    static bool attr_set = false;
    if (!attr_set) {
        cudaFuncSetAttribute(k_gemm1, cudaFuncAttributeMaxDynamicSharedMemorySize,
                             GSMEM_BYTES);
        cudaFuncSetAttribute(k_gemm2, cudaFuncAttributeMaxDynamicSharedMemorySize,
                             GSMEM_BYTES);
        attr_set = true;
    }

    k_zero_cnt<<<(N_NODES + 255) / 256, 256>>>(ei32);
    k_conv_hist<<<(N_EDGES + 255) / 256, 256>>>(ei32);
    k_scan_lb<<<SCAN_NBLK, SCAN_BLK>>>();
    k_scatter<<<(N_EDGES + 255) / 256, 256>>>();

    k_agg1<<<(N_NODES + 7) / 8, 256>>>(x);
    {
        dim3 grid(2, NPAD / 128);
        k_gemm1<<<grid, 256, GSMEM_BYTES>>>(x, w1_l, w1_r, b1_l);
    }
    {
        dim3 grid(2, NPAD / 128);
        k_gemm2<<<grid, 256, GSMEM_BYTES>>>(w2_l, w2_r);
    }
    k_agg2b<<<(N_NODES + 7) / 8, 256>>>(b2_l, out);
}

// round 14
// speedup vs baseline: 1.0422x; 1.0422x over previous
#include <cuda_runtime.h>
#include <cuda_bf16.h>
#include <cstdint>

#define N_NODES 50000
#define N_EDGES 640000
#define NPAD    50048      // 391 * 128
#define SCAN_BLK 512
#define SCAN_NBLK ((N_NODES + SCAN_BLK - 1) / SCAN_BLK)   // 98
#define EPT 4              // edges per thread in conv_hist / scatter

// ---------------- device scratch ----------------------------------------------
__device__ alignas(16)  int   g_is64;
__device__ alignas(16)  int   g_src[N_EDGES];
__device__ alignas(16)  int   g_dst[N_EDGES];
__device__ alignas(16)  int   g_cnt[N_NODES];
__device__ alignas(16)  int   g_rowptr[N_NODES + 1];
__device__ alignas(16)  int   g_fill[N_NODES];
__device__ alignas(16)  int   g_perm[N_EDGES];
__device__ alignas(16)  int   g_bsum[SCAN_NBLK];
__device__ alignas(16)  int   g_boff[SCAN_NBLK];
__device__ alignas(256) float g_mean1[(size_t)NPAD * 128];
__device__ alignas(256) float g_h[(size_t)NPAD * 256];
__device__ alignas(256) float g_pr[(size_t)NPAD * 256];   // [p | r] for layer 2

// ---------------- zero + edge dtype detection (merged) -------------------------
__global__ void k_zero_cnt(const int* __restrict__ ei32) {
    int i = blockIdx.x * blockDim.x + threadIdx.x;
    if (i < N_NODES) g_cnt[i] = 0;
    if (i == 0) {
        int is64 = 1;
        for (int j = 0; j < 64; j++)
            if (ei32[2 * j + 1] != 0) { is64 = 0; break; }
        g_is64 = is64;
    }
}

// 4 edges per thread: int4 loads give 4 independent chains (MLP=4)
__global__ void k_conv_hist(const int* __restrict__ ei32) {
    const int base = (blockIdx.x * blockDim.x + threadIdx.x) * EPT;
    if (base >= N_EDGES) return;
    int sv[EPT], dv[EPT];
    if (g_is64) {
        // int64 pairs: edge i at words {2i, 2i+1}; take low words
        int4 a0 = *(const int4*)&ei32[2 * base];          // edges base..base+1
        int4 a1 = *(const int4*)&ei32[2 * base + 4];      // edges base+2..base+3
        int4 b0 = *(const int4*)&ei32[2 * (N_EDGES + base)];
        int4 b1 = *(const int4*)&ei32[2 * (N_EDGES + base) + 4];
        sv[0] = a0.x; sv[1] = a0.z; sv[2] = a1.x; sv[3] = a1.z;
        dv[0] = b0.x; dv[1] = b0.z; dv[2] = b1.x; dv[3] = b1.z;
    } else {
        int4 a = *(const int4*)&ei32[base];
        int4 b = *(const int4*)&ei32[N_EDGES + base];
        sv[0] = a.x; sv[1] = a.y; sv[2] = a.z; sv[3] = a.w;
        dv[0] = b.x; dv[1] = b.y; dv[2] = b.z; dv[3] = b.w;
    }
#pragma unroll
    for (int j = 0; j < EPT; j++) {
        int s = min(max(sv[j], 0), N_NODES - 1);
        int d = min(max(dv[j], 0), N_NODES - 1);
        g_src[base + j] = s;
        g_dst[base + j] = d;
        atomicAdd(&g_cnt[d], 1);
    }
}

// ---------------- two-level parallel scan (R11 proven) --------------------------
__global__ void k_scan_blk() {
    __shared__ int s[SCAN_BLK];
    const int t = threadIdx.x;
    const int i = blockIdx.x * SCAN_BLK + t;
    const int v = (i < N_NODES) ? g_cnt[i] : 0;
    s[t] = v;
    __syncthreads();
#pragma unroll
    for (int off = 1; off < SCAN_BLK; off <<= 1) {
        int u = 0;
        if (t >= off) u = s[t - off];
        __syncthreads();
        if (t >= off) s[t] += u;
        __syncthreads();
    }
    if (i < N_NODES) g_rowptr[i] = s[t] - v;
    if (t == SCAN_BLK - 1) g_bsum[blockIdx.x] = s[t];
}

__global__ void k_scan_top() {
    __shared__ int s[128];
    const int t = threadIdx.x;
    const int v = (t < SCAN_NBLK) ? g_bsum[t] : 0;
    s[t] = v;
    __syncthreads();
#pragma unroll
    for (int off = 1; off < 128; off <<= 1) {
        int u = 0;
        if (t >= off) u = s[t - off];
        __syncthreads();
        if (t >= off) s[t] += u;
        __syncthreads();
    }
    if (t < SCAN_NBLK) g_boff[t] = s[t] - v;
}

__global__ void k_scan_add() {
    const int i = blockIdx.x * SCAN_BLK + threadIdx.x;
    if (i < N_NODES) {
        const int r = g_rowptr[i] + g_boff[blockIdx.x];
        g_rowptr[i] = r;
        g_fill[i]   = r;
    }
    if (i == 0) g_rowptr[N_NODES] = N_EDGES;
}

// 4 edges per thread (int4 loads), 4 independent atomic chains
__global__ void k_scatter() {
    const int base = (blockIdx.x * blockDim.x + threadIdx.x) * EPT;
    if (base >= N_EDGES) return;
    int4 d4 = *(const int4*)&g_dst[base];
    int4 s4 = *(const int4*)&g_src[base];
    int dv[EPT] = {d4.x, d4.y, d4.z, d4.w};
    int sv[EPT] = {s4.x, s4.y, s4.z, s4.w};
#pragma unroll
    for (int j = 0; j < EPT; j++) {
        int pos = atomicAdd(&g_fill[dv[j]], 1);
        g_perm[pos] = sv[j];
    }
}

// ---------------- layer-1 aggregation: warp per node ---------------------------
__global__ void k_agg1(const float* __restrict__ x) {
    const int node = (blockIdx.x * blockDim.x + threadIdx.x) >> 5;
    const int lane = threadIdx.x & 31;
    if (node >= N_NODES) return;
    const int beg = g_rowptr[node];
    const int end = g_rowptr[node + 1];
    float4 acc = make_float4(0.f, 0.f, 0.f, 0.f);
    for (int e = beg; e < end; e++) {
        const int s = g_perm[e];
        float4 v = ((const float4*)(x + (size_t)s * 128))[lane];
        acc.x += v.x; acc.y += v.y; acc.z += v.z; acc.w += v.w;
    }
    const float inv = 1.0f / (float)max(end - beg, 1);
    acc.x *= inv; acc.y *= inv; acc.z *= inv; acc.w *= inv;
    ((float4*)(g_mean1 + (size_t)node * 128))[lane] = acc;
}

// ---------------- layer-2 aggregation + epilogue -------------------------------
__global__ void k_agg2b(const float* __restrict__ bias, float* __restrict__ out) {
    const int node = (blockIdx.x * blockDim.x + threadIdx.x) >> 5;
    const int lane = threadIdx.x & 31;
    if (node >= N_NODES) return;
    const int beg = g_rowptr[node];
    const int end = g_rowptr[node + 1];
    float4 acc = make_float4(0.f, 0.f, 0.f, 0.f);
    for (int e = beg; e < end; e++) {
        const int s = g_perm[e];
        float4 v = ((const float4*)(g_pr + (size_t)s * 256))[lane];
        acc.x += v.x; acc.y += v.y; acc.z += v.z; acc.w += v.w;
    }
    const float inv = 1.0f / (float)max(end - beg, 1);
    float4 r = ((const float4*)(g_pr + (size_t)node * 256 + 128))[lane];
    float4 b = ((const float4*)bias)[lane];
    float4 o;
    o.x = acc.x * inv + r.x + b.x;
    o.y = acc.y * inv + r.y + b.y;
    o.z = acc.z * inv + r.z + b.z;
    o.w = acc.w * inv + r.w + b.w;
    ((float4*)(out + (size_t)node * 128))[lane] = o;
}

// ---------------- tf32 tensor-core GEMM, cp.async 2-stage pipeline (R11) -------
__device__ __forceinline__ uint32_t f2tf32(float f) {
    uint32_t r;
    asm("cvt.rna.tf32.f32 %0, %1;" : "=r"(r) : "f"(f));
    return r;
}
__device__ __forceinline__ uint32_t bits2tf32(uint32_t b) {
    return f2tf32(__uint_as_float(b));
}

__device__ __forceinline__ void mma_tf32(float d[4], uint32_t a0, uint32_t a1,
                                         uint32_t a2, uint32_t a3,
                                         uint32_t b0, uint32_t b1) {
    asm volatile(
        "mma.sync.aligned.m16n8k8.row.col.f32.tf32.tf32.f32 "
        "{%0,%1,%2,%3}, {%4,%5,%6,%7}, {%8,%9}, {%0,%1,%2,%3};"
        : "+f"(d[0]), "+f"(d[1]), "+f"(d[2]), "+f"(d[3])
        : "r"(a0), "r"(a1), "r"(a2), "r"(a3), "r"(b0), "r"(b1));
}

#define CP_ASYNC16(saddr, gptr) \
    asm volatile("cp.async.cg.shared.global [%0], [%1], 16;" \
                 :: "r"(saddr), "l"(gptr))
#define CP_COMMIT()  asm volatile("cp.async.commit_group;" ::: "memory")
#define CP_WAIT_1()  asm volatile("cp.async.wait_group 1;" ::: "memory")
#define CP_WAIT_0()  asm volatile("cp.async.wait_group 0;" ::: "memory")

constexpr int GBM = 128, GBK = 32;
constexpr int GAS = 36;    // A smem row stride (floats)
constexpr int GBS = 136;   // B smem row stride (floats)
constexpr int GSTAGE = GBM * GAS + GBK * GBS;        // uint32 elems per stage
constexpr int GSMEM_BYTES = 2 * GSTAGE * 4;          // 71680

template <bool RELU>
__device__ __forceinline__ void
tgemm(const float* __restrict__ A1, int K1, const float* __restrict__ B1,
      const float* __restrict__ A2, int K2, const float* __restrict__ B2,
      int ldb, int bofs, const float* __restrict__ bias,
      float* __restrict__ C, int ldc, int Mstore, int Mclamp) {
    extern __shared__ uint32_t smem[];

    const int tid  = threadIdx.x;
    const int wid  = tid >> 5;
    const int lane = tid & 31;
    const int wm = wid & 1;
    const int wn = wid >> 1;
    const int brow = blockIdx.y * GBM;

    const int nk1  = K1 >> 5;
    const int ntot = nk1 + (K2 >> 5);
    const uint32_t smem_u32 = (uint32_t)__cvta_generic_to_shared(smem);

    float acc[4][4][4];
#pragma unroll
    for (int mt = 0; mt < 4; mt++)
#pragma unroll
        for (int nt = 0; nt < 4; nt++)
#pragma unroll
            for (int r = 0; r < 4; r++) acc[mt][nt][r] = 0.f;

#define TG_ISSUE(IT)                                                           \
    do {                                                                       \
        const float* A_; const float* B_; int K_, k0_;                         \
        if ((IT) < nk1) { A_ = A1; B_ = B1; K_ = K1; k0_ = (IT) * GBK; }       \
        else            { A_ = A2; B_ = B2; K_ = K2; k0_ = ((IT) - nk1) * GBK;}\
        const uint32_t sa = smem_u32 + ((IT) & 1) * (GSTAGE * 4);              \
        const uint32_t sb = sa + GBM * GAS * 4;                                \
        _Pragma("unroll")                                                      \
        for (int p = 0; p < 4; p++) {                                          \
            const int idx = tid + p * 256;                                     \
            const int row = idx >> 3;                                          \
            const int c4  = (idx & 7) << 2;                                    \
            const int rg  = min(brow + row, Mclamp - 1);                       \
            CP_ASYNC16(sa + (row * GAS + c4) * 4,                              \
                       &A_[(size_t)rg * K_ + k0_ + c4]);                       \
        }                                                                      \
        _Pragma("unroll")                                                      \
        for (int p = 0; p < 4; p++) {                                          \
            const int idx = tid + p * 256;                                     \
            const int row = idx >> 5;                                          \
            const int c4  = (idx & 31) << 2;                                   \
            CP_ASYNC16(sb + (row * GBS + c4) * 4,                              \
                       &B_[(size_t)(k0_ + row) * ldb + bofs + c4]);            \
        }                                                                      \
        CP_COMMIT();                                                           \
    } while (0)

    TG_ISSUE(0);

#pragma unroll 1
    for (int it = 0; it < ntot; it++) {
        if (it + 1 < ntot) {
            TG_ISSUE(it + 1);
            CP_WAIT_1();       // stage `it` complete
        } else {
            CP_WAIT_0();
        }
        __syncthreads();

        const uint32_t* Asb = smem + (it & 1) * GSTAGE;
        const uint32_t* Bsb = Asb + GBM * GAS;

#pragma unroll
        for (int ks = 0; ks < 4; ks++) {
            const int kk = ks * 8;
            uint32_t af[4][4];
#pragma unroll
            for (int mt = 0; mt < 4; mt++) {
                const int r = wm * 64 + mt * 16 + (lane >> 2);
                const int c = kk + (lane & 3);
                af[mt][0] = bits2tf32(Asb[r * GAS + c]);
                af[mt][1] = bits2tf32(Asb[(r + 8) * GAS + c]);
                af[mt][2] = bits2tf32(Asb[r * GAS + c + 4]);
                af[mt][3] = bits2tf32(Asb[(r + 8) * GAS + c + 4]);
            }
            uint32_t bf[4][2];
#pragma unroll
            for (int nt = 0; nt < 4; nt++) {
                const int n = wn * 32 + nt * 8 + (lane >> 2);
                const int k = kk + (lane & 3);
                bf[nt][0] = bits2tf32(Bsb[k * GBS + n]);
                bf[nt][1] = bits2tf32(Bsb[(k + 4) * GBS + n]);
            }
#pragma unroll
            for (int mt = 0; mt < 4; mt++)
#pragma unroll
                for (int nt = 0; nt < 4; nt++)
                    mma_tf32(acc[mt][nt], af[mt][0], af[mt][1], af[mt][2],
                             af[mt][3], bf[nt][0], bf[nt][1]);
        }
        __syncthreads();
    }
#undef TG_ISSUE

    const int bcolC = blockIdx.x * 128;
#pragma unroll
    for (int nt = 0; nt < 4; nt++) {
        const int col = bcolC + wn * 32 + nt * 8 + ((lane & 3) << 1);
        float bx = 0.f, by = 0.f;
        if (bias) { bx = bias[col]; by = bias[col + 1]; }
#pragma unroll
        for (int mt = 0; mt < 4; mt++) {
            const int row0 = brow + wm * 64 + mt * 16 + (lane >> 2);
            float2 v0, v1;
            v0.x = acc[mt][nt][0] + bx;  v0.y = acc[mt][nt][1] + by;
            v1.x = acc[mt][nt][2] + bx;  v1.y = acc[mt][nt][3] + by;
            if (RELU) {
                v0.x = fmaxf(v0.x, 0.f); v0.y = fmaxf(v0.y, 0.f);
                v1.x = fmaxf(v1.x, 0.f); v1.y = fmaxf(v1.y, 0.f);
            }
            if (row0 < Mstore)
                *(float2*)&C[(size_t)row0 * ldc + col] = v0;
            if (row0 + 8 < Mstore)
                *(float2*)&C[(size_t)(row0 + 8) * ldc + col] = v1;
        }
    }
}

__global__ void __launch_bounds__(256)
k_gemm1(const float* __restrict__ x,
        const float* __restrict__ B1, const float* __restrict__ B2,
        const float* __restrict__ bias) {
    const int bofs = blockIdx.x * 128;
    tgemm<true>(g_mean1, 128, B1, x, 128, B2, 256, bofs, bias,
                g_h, 256, N_NODES, N_NODES);
}

__global__ void __launch_bounds__(256)
k_gemm2(const float* __restrict__ w2l, const float* __restrict__ w2r) {
    const float* B = blockIdx.x ? w2r : w2l;
    tgemm<false>(g_h, 256, B, nullptr, 0, nullptr, 128, 0, nullptr,
                 g_pr, 256, N_NODES, N_NODES);
}

// ---------------- launch -------------------------------------------------------
extern "C" void kernel_launch(void* const* d_in, const int* in_sizes, int n_in,
                              void* d_out, int out_size) {
    const float* x    = (const float*)d_in[0];
    const int*   ei32 = (const int*)d_in[1];
    const float* w1_l = (const float*)d_in[2];
    const float* b1_l = (const float*)d_in[3];
    const float* w1_r = (const float*)d_in[4];
    const float* w2_l = (const float*)d_in[5];
    const float* b2_l = (const float*)d_in[6];
    const float* w2_r = (const float*)d_in[7];
    float* out = (float*)d_out;

    static bool attr_set = false;
    if (!attr_set) {
        cudaFuncSetAttribute(k_gemm1, cudaFuncAttributeMaxDynamicSharedMemorySize,
                             GSMEM_BYTES);
        cudaFuncSetAttribute(k_gemm2, cudaFuncAttributeMaxDynamicSharedMemorySize,
                             GSMEM_BYTES);
        attr_set = true;
    }

    k_zero_cnt<<<(N_NODES + 255) / 256, 256>>>(ei32);
    k_conv_hist<<<(N_EDGES / EPT + 255) / 256, 256>>>(ei32);
    k_scan_blk<<<SCAN_NBLK, SCAN_BLK>>>();
    k_scan_top<<<1, 128>>>();
    k_scan_add<<<SCAN_NBLK, SCAN_BLK>>>();
    k_scatter<<<(N_EDGES / EPT + 255) / 256, 256>>>();

    k_agg1<<<(N_NODES + 7) / 8, 256>>>(x);
    {
        dim3 grid(2, NPAD / 128);
        k_gemm1<<<grid, 256, GSMEM_BYTES>>>(x, w1_l, w1_r, b1_l);
    }
    {
        dim3 grid(2, NPAD / 128);
        k_gemm2<<<grid, 256, GSMEM_BYTES>>>(w2_l, w2_r);
    }
    k_agg2b<<<(N_NODES + 7) / 8, 256>>>(b2_l, out);
}